// round 16
// baseline (speedup 1.0000x reference)
#include <cuda_runtime.h>
#include <cstdint>

#define B_ 256
#define T_ 512
#define D_ 128
#define H_ 128
#define G_ 384          // 3H, gate order z|r|h
#define BT_ (B_*T_)

__device__ float g_xp[(size_t)BT_ * G_];   // 201 MB scratch
__device__ float g_h0[(size_t)BT_ * H_];   // 67 MB scratch

typedef unsigned long long u64;

static __device__ __forceinline__ u64 pack2(float a, float b) {
    u64 r; asm("mov.b64 %0, {%1, %2};" : "=l"(r) : "f"(a), "f"(b)); return r;
}
static __device__ __forceinline__ void unpack2(u64 v, float &a, float &b) {
    asm("mov.b64 {%0, %1}, %2;" : "=f"(a), "=f"(b) : "l"(v));
}
static __device__ __forceinline__ u64 fma2(u64 a, u64 b, u64 c) {
    u64 d; asm("fma.rn.f32x2 %0, %1, %2, %3;" : "=l"(d) : "l"(a), "l"(b), "l"(c)); return d;
}
// MUFU tanh (sm_75+ PTX, not arch-'a' gated)
static __device__ __forceinline__ float tanh_mufu(float x) {
    float r; asm("tanh.approx.f32 %0, %1;" : "=f"(r) : "f"(x)); return r;
}
static __device__ __forceinline__ float sig_mufu(float x) {
    return fmaf(0.5f, tanh_mufu(0.5f * x), 0.5f);
}

// ---------------------------------------------------------------------------
// Projection — VERBATIM R12/R15 (measured ~286us/layer): 256 threads; thread
// (u, kg) owns gate-triple columns {u, u+128, u+256} over its 64-k half.
// Per row: 16 broadcast LDS.128 -> 96 FFMA2 -> 3 shfl.xor(16) -> lane<16 STG.
// ---------------------------------------------------------------------------
__global__ __launch_bounds__(256, 1)
void proj_kernel(const float* __restrict__ x, const float* __restrict__ W,
                 const float* __restrict__ bin, float* __restrict__ out,
                 int rows_per_block)
{
    __shared__ __align__(16) float x_sm[2][8][D_];
    const int tid  = threadIdx.x;
    const int lane = tid & 31;
    const int kg   = lane >> 4;
    const int u    = (tid >> 5) * 16 + (lane & 15);
    const int kb   = kg * 64;

    u64 w[3][32];
#pragma unroll
    for (int i = 0; i < 32; i++)
#pragma unroll
        for (int c = 0; c < 3; c++)
            w[c][i] = pack2(W[(kb + 2*i) * G_ + u + c*128],
                            W[(kb + 2*i + 1) * G_ + u + c*128]);
    const float b0 = bin[u];
    const float b1 = bin[u + 128];
    const float b2 = bin[u + 256];

    const int row0 = blockIdx.x * rows_per_block;
    ((float4*)&x_sm[0][0][0])[tid] = ((const float4*)(x + (size_t)row0 * D_))[tid];
    __syncthreads();

    const int iters = rows_per_block / 8;
    int buf = 0;
    for (int it = 0; it < iters; it++) {
        const int rbase = row0 + it * 8;
        float4 nx;
        const bool pre = (it + 1 < iters);
        if (pre)
            nx = ((const float4*)(x + (size_t)(rbase + 8) * D_))[tid];

#pragma unroll
        for (int r = 0; r < 8; r++) {
            u64 a0 = 0, a1 = 0, a2 = 0;
            const float* xs = &x_sm[buf][r][kb];
#pragma unroll
            for (int i2 = 0; i2 < 16; i2++) {
                ulonglong2 hv = *(const ulonglong2*)&xs[4*i2];
                a0 = fma2(hv.x, w[0][2*i2],     a0);
                a0 = fma2(hv.y, w[0][2*i2 + 1], a0);
                a1 = fma2(hv.x, w[1][2*i2],     a1);
                a1 = fma2(hv.y, w[1][2*i2 + 1], a1);
                a2 = fma2(hv.x, w[2][2*i2],     a2);
                a2 = fma2(hv.y, w[2][2*i2 + 1], a2);
            }
            float pa, pb, pc, pd, pe, pf;
            unpack2(a0, pa, pb);
            unpack2(a1, pc, pd);
            unpack2(a2, pe, pf);
            float s0 = pa + pb, s1 = pc + pd, s2 = pe + pf;
            s0 += __shfl_xor_sync(0xffffffffu, s0, 16);
            s1 += __shfl_xor_sync(0xffffffffu, s1, 16);
            s2 += __shfl_xor_sync(0xffffffffu, s2, 16);
            if (lane < 16) {
                float* o = out + (size_t)(rbase + r) * G_;
                o[u]       = s0 + b0;
                o[u + 128] = s1 + b1;
                o[u + 256] = s2 + b2;
            }
        }
        if (pre)
            ((float4*)&x_sm[buf ^ 1][0][0])[tid] = nx;
        __syncthreads();
        buf ^= 1;
    }
}

// ---------------------------------------------------------------------------
// GRU scan — R15 interleaved shape (380us) + two tail edits:
//  (1) r1's shfl reduction issued BEFORE the h0 store (hides shfl latency),
//  (2) t-loop unrolled x2 (buf constant per copy; cross-step scheduling room).
// ---------------------------------------------------------------------------
__global__ __launch_bounds__(256, 1)
void gru_scan(const float* __restrict__ U, const float* __restrict__ brec,
              const float* __restrict__ xp, float* __restrict__ out)
{
    __shared__ __align__(16) float h_sm[2][2][2][68];  // [buf][row][kg][pad]
    const int tid  = threadIdx.x;
    const int lane = tid & 31;
    const int kg   = lane >> 4;
    const int u    = (tid >> 5) * 16 + (lane & 15);
    const int kb   = kg * 64;

    u64 w[3][32];
#pragma unroll
    for (int i = 0; i < 32; i++)
#pragma unroll
        for (int c = 0; c < 3; c++)
            w[c][i] = pack2(U[(kb + 2*i) * G_ + u + c*128],
                            U[(kb + 2*i + 1) * G_ + u + c*128]);
    const float bz = brec[u], br_ = brec[u + 128], bh = brec[u + 256];

    const int row = kg;                 // this thread's gate row
    const int b0  = blockIdx.x * 2;
    const float* exr = xp + (size_t)(b0 + row) * T_ * G_;
    float* eo = out + (size_t)(b0 + row) * T_ * H_;

    float xz  = exr[u];
    float xr_ = exr[u + 128];
    float xh  = exr[u + 256];
    float hp  = 0.0f;

    if (tid < 128) {
        h_sm[0][0][tid >> 6][tid & 63] = 0.0f;
        h_sm[0][1][tid >> 6][tid & 63] = 0.0f;
    }
    __syncthreads();

#pragma unroll 2
    for (int t = 0; t < T_; t++) {
        const int buf = t & 1;
        float nxz = 0.f, nxr = 0.f, nxh = 0.f;
        if (t + 1 < T_) {
            const float* xn = exr + (size_t)(t + 1) * G_;
            nxz = xn[u]; nxr = xn[u + 128]; nxh = xn[u + 256];
        }

        // ---- matvec row 0 ----
        u64 a0 = 0, a1 = 0, a2 = 0;
        {
            const float* hs = &h_sm[buf][0][kg][0];
#pragma unroll
            for (int i2 = 0; i2 < 16; i2++) {
                ulonglong2 hv = *(const ulonglong2*)&hs[4*i2];
                a0 = fma2(hv.x, w[0][2*i2], a0);
                a0 = fma2(hv.y, w[0][2*i2 + 1], a0);
                a1 = fma2(hv.x, w[1][2*i2], a1);
                a1 = fma2(hv.y, w[1][2*i2 + 1], a1);
                a2 = fma2(hv.x, w[2][2*i2], a2);
                a2 = fma2(hv.y, w[2][2*i2 + 1], a2);
            }
        }
        // ---- reduce + gates row 0 (kg==0 lanes own row 0) ----
        float hn0 = 0.0f;
        {
            float pa, pb, pc, pd, pe, pf;
            unpack2(a0, pa, pb); unpack2(a1, pc, pd); unpack2(a2, pe, pf);
            float s0 = pa + pb, s1 = pc + pd, s2 = pe + pf;
            s0 += __shfl_xor_sync(0xffffffffu, s0, 16);
            s1 += __shfl_xor_sync(0xffffffffu, s1, 16);
            s2 += __shfl_xor_sync(0xffffffffu, s2, 16);
            if (kg == 0) {
                float z  = sig_mufu(xz + s0 + bz);
                float rg = sig_mufu(xr_ + s1 + br_);
                float hh = tanh_mufu(xh + rg * (s2 + bh));
                hn0 = hh + z * (hp - hh);
            }
        }

        // ---- matvec row 1 (hides row 0's shfl/MUFU latency) ----
        u64 c0 = 0, c1 = 0, c2 = 0;
        {
            const float* hs = &h_sm[buf][1][kg][0];
#pragma unroll
            for (int i2 = 0; i2 < 16; i2++) {
                ulonglong2 hv = *(const ulonglong2*)&hs[4*i2];
                c0 = fma2(hv.x, w[0][2*i2], c0);
                c0 = fma2(hv.y, w[0][2*i2 + 1], c0);
                c1 = fma2(hv.x, w[1][2*i2], c1);
                c1 = fma2(hv.y, w[1][2*i2 + 1], c1);
                c2 = fma2(hv.x, w[2][2*i2], c2);
                c2 = fma2(hv.y, w[2][2*i2 + 1], c2);
            }
        }
        // ---- r1 shfl reduction FIRST (latency hidden under h0 store) ----
        float t0, t1, t2v;
        {
            float pa, pb, pc, pd, pe, pf;
            unpack2(c0, pa, pb); unpack2(c1, pc, pd); unpack2(c2, pe, pf);
            t0 = pa + pb; t1 = pc + pd; t2v = pe + pf;
            t0  += __shfl_xor_sync(0xffffffffu, t0, 16);
            t1  += __shfl_xor_sync(0xffffffffu, t1, 16);
            t2v += __shfl_xor_sync(0xffffffffu, t2v, 16);
        }
        // ---- store h0 results ----
        if (kg == 0) {
            hp = hn0;
            h_sm[buf ^ 1][0][u >> 6][u & 63] = hn0;
            eo[(size_t)t * H_ + u] = hn0;
        }
        // ---- gates + store row 1 (kg==1 lanes own row 1) ----
        if (kg == 1) {
            float z  = sig_mufu(xz + t0 + bz);
            float rg = sig_mufu(xr_ + t1 + br_);
            float hh = tanh_mufu(xh + rg * (t2v + bh));
            float hn = hh + z * (hp - hh);
            hp = hn;
            h_sm[buf ^ 1][1][u >> 6][u & 63] = hn;
            eo[(size_t)t * H_ + u] = hn;
        }
        xz = nxz; xr_ = nxr; xh = nxh;
        __syncthreads();
    }
}

// ---------------------------------------------------------------------------
extern "C" void kernel_launch(void* const* d_in, const int* in_sizes, int n_in,
                              void* d_out, int out_size)
{
    const float* x  = (const float*)d_in[0];
    const float* W0 = (const float*)d_in[1];
    const float* U0 = (const float*)d_in[2];
    const float* b0 = (const float*)d_in[3];
    const float* W1 = (const float*)d_in[4];
    const float* U1 = (const float*)d_in[5];
    const float* b1 = (const float*)d_in[6];
    float* out = (float*)d_out;

    float *xp, *h0;
    cudaGetSymbolAddress((void**)&xp, g_xp);
    cudaGetSymbolAddress((void**)&h0, g_h0);

    const int PROJ_GRID = 1024;
    const int rpb = BT_ / PROJ_GRID;   // 128 rows per block

    // layer 0
    proj_kernel<<<PROJ_GRID, 256>>>(x, W0, b0, xp, rpb);
    gru_scan<<<B_ / 2, 256>>>(U0, b0 + G_, xp, h0);
    // layer 1
    proj_kernel<<<PROJ_GRID, 256>>>(h0, W1, b1, xp, rpb);
    gru_scan<<<B_ / 2, 256>>>(U1, b1 + G_, xp, out);
}